// round 14
// baseline (speedup 1.0000x reference)
#include <cuda_runtime.h>
#include <cuda_fp16.h>
#include <math.h>

#define NU 100000
#define NI 50000
#define NE 120000
#define NR 32
#define DM 64
#define NEDGE 1000000
#define NCF 1000000

#define SEG_U 120000
#define SEG_I 220000
#define NSEG 270000
#define SCAN_N 270001
#define SCAN_BLK 1024
#define SCAN_NBLK 264

#define USER_BLOCKS 12500         // NU/8
#define ITEM_BLOCKS 6250          // NI/8
#define ENT_BLOCKS 15000          // NE/8

__device__ int   g_cnt[SCAN_NBLK * SCAN_BLK];
__device__ int   g_off[SCAN_NBLK * SCAN_BLK + 1];
__device__ int   g_cur[NSEG];
__device__ int   g_perm[NEDGE + 2 * NCF];   // PAYLOADS: entity=(tail<<5)|type, user=col, item=row
__device__ int   g_bsum[SCAN_BLK];

__device__ float g_entA[NE * DM];
__device__ float g_entB[NE * DM];
__device__ float g_u[NU * DM];
__device__ float g_ucf0[NU * DM];
__device__ float g_ucf1[NU * DM];
__device__ float g_p[NCF];
__device__ float g_pcf[NCF];

// transposed weight matrices (Wt[k*64+d] = W[d*64+k]), per hop
__device__ float g_W1t[2][DM * DM];
__device__ float g_W2t[2][DM * DM];

// half item tables gathered by the user path; ALL double-buffered per hop
// (entity(h+1) runs concurrently with user(h) in the mega launch)
__device__ __half g_relkg_h[2][NI * DM];
__device__ __half g_kg_h[2][NI * DM];
__device__ __half g_icf_h[2][NI * DM];

__device__ __forceinline__ float warpsum(float v) {
    #pragma unroll
    for (int o = 16; o; o >>= 1) v += __shfl_xor_sync(0xffffffffu, v, o);
    return v;
}
__device__ __forceinline__ float lrelu(float x) { return x > 0.f ? x : 0.01f * x; }
__device__ __forceinline__ float sigmoidf(float x) { return 1.f / (1.f + __expf(-x)); }

// ---------------- setup kernels ----------------
__global__ void k_init(const float* __restrict__ ue, const float* __restrict__ ee,
                       const float* __restrict__ cf,
                       const float* __restrict__ W1, const float* __restrict__ W2,
                       float* __restrict__ out) {
    const int total = (NE + NU + NU + NI) * DM;
    for (int i = blockIdx.x * blockDim.x + threadIdx.x; i < total; i += gridDim.x * blockDim.x) {
        if (i < SCAN_NBLK * SCAN_BLK) {
            g_cnt[i] = 0;
            if (i < NSEG) g_cur[i] = 0;
        }
        if (i < 2 * DM * DM) {              // transpose both hops' W1/W2
            int h = i >> 12, r = i & 4095;
            int d = r >> 6, k = r & 63;
            g_W1t[h][k * 64 + d] = W1[h * 4096 + d * 64 + k];
            g_W2t[h][k * 64 + d] = W2[h * 4096 + d * 64 + k];
        }
        float v;
        if (i < NE * DM)                   v = ee[i];
        else if (i < (NE + NU) * DM)       v = ue[i - NE * DM];
        else if (i < (NE + 2 * NU) * DM)   v = cf[i - (NE + NU) * DM];
        else {
            int d = i - (NE + 2 * NU) * DM;
            v = cf[NU * DM + d];
            g_icf_h[0][d] = __float2half(v);
        }
        out[i] = v;
    }
}

__global__ void k_count(const int* __restrict__ heads, const int* __restrict__ imat) {
    for (int i = blockIdx.x * blockDim.x + threadIdx.x; i < NEDGE; i += gridDim.x * blockDim.x) {
        atomicAdd(&g_cnt[heads[i]], 1);
        atomicAdd(&g_cnt[SEG_U + imat[2 * i]], 1);
        atomicAdd(&g_cnt[SEG_I + imat[2 * i + 1]], 1);
    }
}

__global__ void k_scan1() {
    __shared__ int sh[SCAN_BLK];
    int t = threadIdx.x;
    int i = blockIdx.x * SCAN_BLK + t;
    sh[t] = (i < SCAN_N) ? g_cnt[i] : 0;
    __syncthreads();
    for (int s = SCAN_BLK / 2; s > 0; s >>= 1) {
        if (t < s) sh[t] += sh[t + s];
        __syncthreads();
    }
    if (t == 0) g_bsum[blockIdx.x] = sh[0];
}

__global__ void k_scanB() {
    __shared__ int sb[SCAN_BLK];
    __shared__ int sh[SCAN_BLK];
    int t = threadIdx.x;
    int v0 = (t < SCAN_NBLK) ? g_bsum[t] : 0;
    sb[t] = v0;
    __syncthreads();
    for (int d = 1; d < SCAN_BLK; d <<= 1) {
        int x = (t >= d) ? sb[t - d] : 0;
        __syncthreads();
        sb[t] += x;
        __syncthreads();
    }
    int boff = (blockIdx.x == 0) ? 0 : sb[blockIdx.x - 1];

    int i = blockIdx.x * SCAN_BLK + t;
    int v = (i < SCAN_N) ? g_cnt[i] : 0;
    sh[t] = v;
    __syncthreads();
    for (int d = 1; d < SCAN_BLK; d <<= 1) {
        int x = (t >= d) ? sh[t - d] : 0;
        __syncthreads();
        sh[t] += x;
        __syncthreads();
    }
    if (i < SCAN_N) g_off[i] = boff + sh[t] - v;
}

__global__ void k_scatter(const int* __restrict__ heads, const int* __restrict__ tails,
                          const int* __restrict__ etype, const int* __restrict__ imat) {
    for (int i = blockIdx.x * blockDim.x + threadIdx.x; i < NEDGE; i += gridDim.x * blockDim.x) {
        int h = heads[i];
        int p = g_off[h] + atomicAdd(&g_cur[h], 1);
        g_perm[p] = (tails[i] << 5) | etype[i];
        int row = imat[2 * i], col = imat[2 * i + 1];
        int r = SEG_U + row;
        p = g_off[r] + atomicAdd(&g_cur[r], 1);
        g_perm[p] = col;
        int c = SEG_I + col;
        p = g_off[c] + atomicAdd(&g_cur[c], 1);
        g_perm[p] = row;
    }
}

// ---------------- work bodies (shared by standalone + mega kernels) ----------------

// entity: warp-per-entity, s_rel in smem (8KB), transposed weights via L1.
__device__ __forceinline__ void entity_body(
        int t, int e, int hop,
        const float* __restrict__ ext_ent, const float* __restrict__ relw,
        const float* __restrict__ B1, const float* __restrict__ B2,
        float* __restrict__ out, float* s_rel)
{
    for (int i = t; i < NR * DM; i += 256) s_rel[i] = relw[i];
    __syncthreads();

    if (e >= NE) return;
    const float* entin = hop ? g_entB : ext_ent;
    float* entout      = hop ? g_entA : g_entB;
    const float* Wt1 = g_W1t[hop];
    const float* Wt2 = g_W2t[hop];
    const float* b1 = B1 + hop * DM;
    const float* b2 = B2 + hop * DM;
    __half* relkg_h = g_relkg_h[hop];
    __half* kg_h    = g_kg_h[hop];

    int lane = t & 31;
    int p0 = g_off[e], p1 = g_off[e + 1];
    bool eItem = e < NI;

    float a10 = 0, a11 = 0, a20 = 0, a21 = 0, ar0 = 0, ar1 = 0;
    int nc = 0;
    for (int p = p0; p < p1; p++) {
        int packed = g_perm[p];
        int tl = packed >> 5, ty = packed & 31;
        float r0 = s_rel[ty * 64 + lane], r1 = s_rel[ty * 64 + 32 + lane];
        float t0 = entin[tl * 64 + lane], t1 = entin[tl * 64 + 32 + lane];
        bool cross = eItem != (tl < NI);
        if (cross) { a10 += t0 * r0; a11 += t1 * r1; nc++; }
        else       { a20 += t0 + r0; a21 += t1 + r1; }
        ar0 += r0; ar1 += r1;
    }
    int n = p1 - p0;

    if (eItem) {
        float dn = 1.f / fmaxf((float)n, 1.f);
        float e0 = entin[e * 64 + lane], e1 = entin[e * 64 + 32 + lane];
        relkg_h[e * 64 + lane]      = __float2half((ar0 * dn) * e0);
        relkg_h[e * 64 + 32 + lane] = __float2half((ar1 * dn) * e1);
        kg_h[e * 64 + lane]         = __float2half(e0);
        kg_h[e * 64 + 32 + lane]    = __float2half(e1);
    }

    float i1 = 1.f / fmaxf((float)nc, 1.f);
    float i2 = 1.f / fmaxf((float)(n - nc), 1.f);
    a10 *= i1; a11 *= i1; a20 *= i2; a21 *= i2;

    float o10 = __ldg(&b1[lane]), o11 = __ldg(&b1[lane + 32]);
    float o20 = __ldg(&b2[lane]), o21 = __ldg(&b2[lane + 32]);
    #pragma unroll
    for (int k = 0; k < 64; k++) {
        float a1 = __shfl_sync(0xffffffffu, (k < 32) ? a10 : a11, k & 31);
        float a2 = __shfl_sync(0xffffffffu, (k < 32) ? a20 : a21, k & 31);
        o10 += a1 * __ldg(&Wt1[k * 64 + lane]);
        o11 += a1 * __ldg(&Wt1[k * 64 + 32 + lane]);
        o20 += a2 * __ldg(&Wt2[k * 64 + lane]);
        o21 += a2 * __ldg(&Wt2[k * 64 + 32 + lane]);
    }
    float v0 = 0.5f * (lrelu(o10) + lrelu(o20));
    float v1 = 0.5f * (lrelu(o11) + lrelu(o21));
    float ss = warpsum(v0 * v0 + v1 * v1);
    float inv = 1.f / fmaxf(sqrtf(ss), 1e-12f);
    v0 *= inv; v1 *= inv;
    entout[e * 64 + lane] = v0;
    entout[e * 64 + 32 + lane] = v1;
    out[e * 64 + lane] += v0;
    out[e * 64 + 32 + lane] += v1;
}

// item: warp-per-item seg mean of ucf rows; writes next hop's icf half table.
__device__ __forceinline__ void item_body(
        int lane, int c, int hop,
        const float* __restrict__ ext_ucf, float* __restrict__ out)
{
    if (c >= NI) return;
    const float2* ucfin2 = (const float2*)(hop ? g_ucf0 : ext_ucf);
    float2* out2 = (float2*)out;
    int p0 = g_off[SEG_I + c], p1 = g_off[SEG_I + c + 1];
    float2 acc = make_float2(0.f, 0.f);
    for (int p = p0; p < p1; p++) {
        int row = g_perm[p];
        float2 v = ucfin2[row * 32 + lane];
        acc.x += v.x; acc.y += v.y;
    }
    float dn = 1.f / fmaxf((float)(p1 - p0), 1.f);
    acc.x *= dn; acc.y *= dn;
    float ss = warpsum(acc.x * acc.x + acc.y * acc.y);
    float inv = 1.f / fmaxf(sqrtf(ss), 1e-12f);
    acc.x *= inv; acc.y *= inv;
    ((__half2*)g_icf_h[(hop + 1) & 1])[c * 32 + lane] = __floats2half2_rn(acc.x, acc.y);
    int ob = (NE + 2 * NU) * 32 + c * 32 + lane;
    float2 o = out2[ob];
    o.x += acc.x; o.y += acc.y;
    out2[ob] = o;
}

// user: warp-per-user 3-iteration attention (R11/R12-proven structure).
__device__ __forceinline__ void user_body(
        int lane, int u, int hop, float* sw_base,
        const float* __restrict__ ext_user, const float* __restrict__ ext_ucf,
        float* __restrict__ out)
{
    const __half* icf_tab = g_icf_h[hop & 1];
    const uint4* rkh4    = (const uint4*)g_relkg_h[hop];
    const uint4* icfh4   = (const uint4*)icf_tab;
    const __half2* rkh2  = (const __half2*)g_relkg_h[hop];
    const __half2* kgh2  = (const __half2*)g_kg_h[hop];
    const __half2* icfh2 = (const __half2*)icf_tab;
    const float* usrc    = hop ? g_u    : ext_user;
    const float* ucfsrc  = hop ? g_ucf0 : ext_ucf;
    float2* udst2   = (float2*)g_u;
    float2* ucfdst2 = (float2*)(hop ? g_ucf1 : g_ucf0);
    float2* out2    = (float2*)out;

    if (u >= NU) return;
    float* sU  = sw_base;
    float* sUC = sU + 64;
    float* sW  = sU + 128;
    float* sWC = sU + 192;
    int*   sCol = (int*)(sU + 256);

    int p0 = g_off[SEG_U + u];
    int n  = g_off[SEG_U + u + 1] - p0;
    if (n == 0) {
        float2 z = make_float2(0.f, 0.f);
        udst2[u * 32 + lane] = z;
        ucfdst2[u * 32 + lane] = z;
        return;
    }
    int pb = p0 - NEDGE;
    int nin = n < 64 ? n : 64;

    sU[lane]       = usrc[u * 64 + lane];
    sU[32 + lane]  = usrc[u * 64 + 32 + lane];
    sUC[lane]      = ucfsrc[u * 64 + lane];
    sUC[32 + lane] = ucfsrc[u * 64 + 32 + lane];
    if (lane < nin)      sCol[lane]      = g_perm[p0 + lane];
    if (lane + 32 < nin) sCol[lane + 32] = g_perm[p0 + lane + 32];
    __syncwarp();

    float2 ud, cd;
    int li = lane & 7, g = lane >> 3;

    for (int it = 0; it < 3; it++) {
        for (int jb = 0; jb < nin; jb += 4) {
            int j = jb + g;
            bool act = j < nin;
            int col = act ? sCol[j] : 0;
            uint4 ra = rkh4[col * 8 + li];
            uint4 ba = icfh4[col * 8 + li];
            float2 r0 = __half22float2(*(const __half2*)&ra.x);
            float2 r1 = __half22float2(*(const __half2*)&ra.y);
            float2 r2 = __half22float2(*(const __half2*)&ra.z);
            float2 r3 = __half22float2(*(const __half2*)&ra.w);
            float2 b0 = __half22float2(*(const __half2*)&ba.x);
            float2 b1 = __half22float2(*(const __half2*)&ba.y);
            float2 b2 = __half22float2(*(const __half2*)&ba.z);
            float2 b3 = __half22float2(*(const __half2*)&ba.w);
            float4 u0 = *(const float4*)(sU + 8 * li);
            float4 u1 = *(const float4*)(sU + 8 * li + 4);
            float4 c0 = *(const float4*)(sUC + 8 * li);
            float4 c1 = *(const float4*)(sUC + 8 * li + 4);
            float s  = r0.x*u0.x + r0.y*u0.y + r1.x*u0.z + r1.y*u0.w
                     + r2.x*u1.x + r2.y*u1.y + r3.x*u1.z + r3.y*u1.w;
            float sc = b0.x*c0.x + b0.y*c0.y + b1.x*c0.z + b1.y*c0.w
                     + b2.x*c1.x + b2.y*c1.y + b3.x*c1.z + b3.y*c1.w;
            s  += __shfl_xor_sync(0xffffffffu, s, 1);
            sc += __shfl_xor_sync(0xffffffffu, sc, 1);
            s  += __shfl_xor_sync(0xffffffffu, s, 2);
            sc += __shfl_xor_sync(0xffffffffu, sc, 2);
            s  += __shfl_xor_sync(0xffffffffu, s, 4);
            sc += __shfl_xor_sync(0xffffffffu, sc, 4);
            if (li == 0 && act) { sW[j] = s; sWC[j] = sc; }
        }
        for (int j = 64; j < n; j++) {   // fallback (not taken for this data)
            int col = g_perm[p0 + j];
            float2 rk = __half22float2(rkh2[col * 32 + lane]);
            float2 iv = __half22float2(icfh2[col * 32 + lane]);
            float s  = warpsum(rk.x * sU[2 * lane] + rk.y * sU[2 * lane + 1]);
            float sc = warpsum(iv.x * sUC[2 * lane] + iv.y * sUC[2 * lane + 1]);
            if (lane == 0) { g_p[pb + j] = s; g_pcf[pb + j] = sc; }
        }
        __syncwarp();
        float se = 0.f, sec = 0.f;
        if (lane < nin) {
            float e  = __expf(sigmoidf(sW[lane]));
            float ec = __expf(sigmoidf(sWC[lane]));
            sW[lane] = e; sWC[lane] = ec; se += e; sec += ec;
        }
        if (lane + 32 < nin) {
            float e  = __expf(sigmoidf(sW[lane + 32]));
            float ec = __expf(sigmoidf(sWC[lane + 32]));
            sW[lane + 32] = e; sWC[lane + 32] = ec; se += e; sec += ec;
        }
        for (int j = 64 + lane; j < n; j += 32) {
            float e  = __expf(sigmoidf(g_p[pb + j]));
            float ec = __expf(sigmoidf(g_pcf[pb + j]));
            g_p[pb + j] = e; g_pcf[pb + j] = ec;
            se += e; sec += ec;
        }
        se = warpsum(se); sec = warpsum(sec);
        float inv = 1.f / se, invc = 1.f / sec;
        __syncwarp();
        float2 A = make_float2(0.f, 0.f), B = make_float2(0.f, 0.f);
        for (int j = 0; j < nin; j++) {
            int col = sCol[j];
            float wp = sW[j] * inv, wc = sWC[j] * invc;
            float2 gv = __half22float2(kgh2[col * 32 + lane]);
            float2 iv = __half22float2(icfh2[col * 32 + lane]);
            A.x += wp * gv.x; A.y += wp * gv.y;
            B.x += wc * iv.x; B.y += wc * iv.y;
        }
        for (int j = 64; j < n; j++) {
            float wp = g_p[pb + j] * inv, wc = g_pcf[pb + j] * invc;
            int col = g_perm[p0 + j];
            float2 gv = __half22float2(kgh2[col * 32 + lane]);
            float2 iv = __half22float2(icfh2[col * 32 + lane]);
            A.x += wp * gv.x; A.y += wp * gv.y;
            B.x += wc * iv.x; B.y += wc * iv.y;
        }
        float ss = warpsum(A.x * A.x + A.y * A.y);
        float i1 = 1.f / fmaxf(sqrtf(ss), 1e-12f);
        ss = warpsum(B.x * B.x + B.y * B.y);
        float i2 = 1.f / fmaxf(sqrtf(ss), 1e-12f);
        ud.x = A.x * i1; ud.y = A.y * i1;
        cd.x = B.x * i2; cd.y = B.y * i2;
        if (it < 2) {
            __syncwarp();
            sU[2 * lane] = ud.x;  sU[2 * lane + 1] = ud.y;
            sUC[2 * lane] = cd.x; sUC[2 * lane + 1] = cd.y;
            __syncwarp();
        }
    }

    udst2[u * 32 + lane] = ud;
    ucfdst2[u * 32 + lane] = cd;
    int o1 = NE * 32 + u * 32 + lane;
    float2 o = out2[o1]; o.x += ud.x; o.y += ud.y; out2[o1] = o;
    int o2 = (NE + NU) * 32 + u * 32 + lane;
    o = out2[o2]; o.x += cd.x; o.y += cd.y; out2[o2] = o;
}

// ---------------- kernels ----------------

// hop-0 entity (standalone)
__global__ void __launch_bounds__(256) k_entity0(
        const float* __restrict__ ext_ent, const float* __restrict__ relw,
        const float* __restrict__ B1, const float* __restrict__ B2,
        float* __restrict__ out) {
    __shared__ float s_rel[NR * DM];
    int t = threadIdx.x;
    entity_body(t, blockIdx.x * 8 + (t >> 5), 0, ext_ent, relw, B1, B2, out, s_rel);
}

// mega launch: user(0) + item(0) + entity(1) — all mutually independent
__global__ void __launch_bounds__(256) k_mega(
        const float* __restrict__ ext_user, const float* __restrict__ ext_ucf,
        const float* __restrict__ ext_ent, const float* __restrict__ relw,
        const float* __restrict__ B1, const float* __restrict__ B2,
        float* __restrict__ out) {
    __shared__ __align__(16) float sm[8 * 320];   // user: per-warp 320; entity: first 2048 = s_rel
    int t = threadIdx.x;
    int w = t >> 5, lane = t & 31;
    if (blockIdx.x < USER_BLOCKS) {
        user_body(lane, blockIdx.x * 8 + w, 0, sm + w * 320, ext_user, ext_ucf, out);
    } else if (blockIdx.x < USER_BLOCKS + ITEM_BLOCKS) {
        item_body(lane, (blockIdx.x - USER_BLOCKS) * 8 + w, 0, ext_ucf, out);
    } else {
        entity_body(t, (blockIdx.x - USER_BLOCKS - ITEM_BLOCKS) * 8 + w, 1,
                    ext_ent, relw, B1, B2, out, sm);
    }
}

// hop-1 user + item
__global__ void __launch_bounds__(256) k_useritem1(
        const float* __restrict__ ext_user, const float* __restrict__ ext_ucf,
        float* __restrict__ out) {
    __shared__ __align__(16) float sm[8 * 320];
    int t = threadIdx.x;
    int w = t >> 5, lane = t & 31;
    if (blockIdx.x < USER_BLOCKS) {
        user_body(lane, blockIdx.x * 8 + w, 1, sm + w * 320, ext_user, ext_ucf, out);
    } else {
        item_body(lane, (blockIdx.x - USER_BLOCKS) * 8 + w, 1, ext_ucf, out);
    }
}

extern "C" void kernel_launch(void* const* d_in, const int* in_sizes, int n_in,
                              void* d_out, int out_size) {
    const float* user_emb = (const float*)d_in[0];
    const float* entity_emb = (const float*)d_in[1];
    const float* emb_cf = (const float*)d_in[2];
    const float* relw = (const float*)d_in[3];
    const float* W1 = (const float*)d_in[4];
    const float* B1 = (const float*)d_in[5];
    const float* W2 = (const float*)d_in[6];
    const float* B2 = (const float*)d_in[7];
    const int* eidx = (const int*)d_in[8];
    const int* etype = (const int*)d_in[9];
    const int* imat = (const int*)d_in[10];
    float* out = (float*)d_out;

    const int* heads = eidx;
    const int* tails = eidx + NEDGE;
    const float* ucf_ext = emb_cf;

    k_init<<<2048, 256>>>(user_emb, entity_emb, emb_cf, W1, W2, out);
    k_count<<<3907, 256>>>(heads, imat);
    k_scan1<<<SCAN_NBLK, SCAN_BLK>>>();
    k_scanB<<<SCAN_NBLK, SCAN_BLK>>>();
    k_scatter<<<3907, 256>>>(heads, tails, etype, imat);

    k_entity0<<<ENT_BLOCKS, 256>>>(entity_emb, relw, B1, B2, out);
    k_mega<<<USER_BLOCKS + ITEM_BLOCKS + ENT_BLOCKS, 256>>>(
        user_emb, ucf_ext, entity_emb, relw, B1, B2, out);
    k_useritem1<<<USER_BLOCKS + ITEM_BLOCKS, 256>>>(user_emb, ucf_ext, out);

    (void)in_sizes; (void)n_in; (void)out_size;
}

// round 15
// speedup vs baseline: 1.0875x; 1.0875x over previous
#include <cuda_runtime.h>
#include <cuda_fp16.h>
#include <math.h>

#define NU 100000
#define NI 50000
#define NE 120000
#define NR 32
#define DM 64
#define NEDGE 1000000
#define NCF 1000000

#define SEG_U 120000
#define SEG_I 220000
#define NSEG 270000
#define SCAN_N 270001
#define SCAN_BLK 1024
#define SCAN_NBLK 264

#define USER_BLOCKS 12500         // NU/8
#define ITEM_BLOCKS 6250          // NI/8

__device__ int   g_cnt[SCAN_NBLK * SCAN_BLK];
__device__ int   g_off[SCAN_NBLK * SCAN_BLK + 1];
__device__ int   g_cur[NSEG];
__device__ int   g_perm[NEDGE + 2 * NCF];   // PAYLOADS: entity=(tail<<5)|type, user=col, item=row
__device__ int   g_bsum[SCAN_BLK];

__device__ float g_entA[NE * DM];
__device__ float g_entB[NE * DM];
__device__ float g_u[NU * DM];
__device__ float g_ucf0[NU * DM];
__device__ float g_ucf1[NU * DM];
__device__ float g_p[NCF];
__device__ float g_pcf[NCF];

// transposed weight matrices (Wt[k*64+d] = W[d*64+k]), per hop
__device__ float g_W1t[2][DM * DM];
__device__ float g_W2t[2][DM * DM];

// half item tables gathered by k_useritem (col < NI only); icf double-buffered
__device__ __half g_relkg_h[NI * DM];
__device__ __half g_kg_h[NI * DM];
__device__ __half g_icf_h[2][NI * DM];

__device__ __forceinline__ float warpsum(float v) {
    #pragma unroll
    for (int o = 16; o; o >>= 1) v += __shfl_xor_sync(0xffffffffu, v, o);
    return v;
}
__device__ __forceinline__ float lrelu(float x) { return x > 0.f ? x : 0.01f * x; }
__device__ __forceinline__ float sigmoidf(float x) { return 1.f / (1.f + __expf(-x)); }

// init: out = concat(...) + zero counters + seed icf_h[0] + transpose weights
__global__ void k_init(const float* __restrict__ ue, const float* __restrict__ ee,
                       const float* __restrict__ cf,
                       const float* __restrict__ W1, const float* __restrict__ W2,
                       float* __restrict__ out) {
    const int total = (NE + NU + NU + NI) * DM;
    for (int i = blockIdx.x * blockDim.x + threadIdx.x; i < total; i += gridDim.x * blockDim.x) {
        if (i < SCAN_NBLK * SCAN_BLK) {
            g_cnt[i] = 0;
            if (i < NSEG) g_cur[i] = 0;
        }
        if (i < 2 * DM * DM) {              // transpose both hops' W1/W2
            int h = i >> 12, r = i & 4095;
            int d = r >> 6, k = r & 63;
            g_W1t[h][k * 64 + d] = W1[h * 4096 + d * 64 + k];
            g_W2t[h][k * 64 + d] = W2[h * 4096 + d * 64 + k];
        }
        float v;
        if (i < NE * DM)                   v = ee[i];
        else if (i < (NE + NU) * DM)       v = ue[i - NE * DM];
        else if (i < (NE + 2 * NU) * DM)   v = cf[i - (NE + NU) * DM];
        else {
            int d = i - (NE + 2 * NU) * DM;
            v = cf[NU * DM + d];
            g_icf_h[0][d] = __float2half(v);
        }
        out[i] = v;
    }
}

__global__ void k_count(const int* __restrict__ heads, const int2* __restrict__ imat2) {
    for (int i = blockIdx.x * blockDim.x + threadIdx.x; i < NEDGE; i += gridDim.x * blockDim.x) {
        int2 rc = imat2[i];
        atomicAdd(&g_cnt[heads[i]], 1);
        atomicAdd(&g_cnt[SEG_U + rc.x], 1);
        atomicAdd(&g_cnt[SEG_I + rc.y], 1);
    }
}

__global__ void k_scan1() {
    __shared__ int sh[SCAN_BLK];
    int t = threadIdx.x;
    int i = blockIdx.x * SCAN_BLK + t;
    sh[t] = (i < SCAN_N) ? g_cnt[i] : 0;
    __syncthreads();
    for (int s = SCAN_BLK / 2; s > 0; s >>= 1) {
        if (t < s) sh[t] += sh[t + s];
        __syncthreads();
    }
    if (t == 0) g_bsum[blockIdx.x] = sh[0];
}

// fused scan2+scan3
__global__ void k_scanB() {
    __shared__ int sb[SCAN_BLK];
    __shared__ int sh[SCAN_BLK];
    int t = threadIdx.x;
    int v0 = (t < SCAN_NBLK) ? g_bsum[t] : 0;
    sb[t] = v0;
    __syncthreads();
    for (int d = 1; d < SCAN_BLK; d <<= 1) {
        int x = (t >= d) ? sb[t - d] : 0;
        __syncthreads();
        sb[t] += x;
        __syncthreads();
    }
    int boff = (blockIdx.x == 0) ? 0 : sb[blockIdx.x - 1];

    int i = blockIdx.x * SCAN_BLK + t;
    int v = (i < SCAN_N) ? g_cnt[i] : 0;
    sh[t] = v;
    __syncthreads();
    for (int d = 1; d < SCAN_BLK; d <<= 1) {
        int x = (t >= d) ? sh[t - d] : 0;
        __syncthreads();
        sh[t] += x;
        __syncthreads();
    }
    if (i < SCAN_N) g_off[i] = boff + sh[t] - v;
}

__global__ void k_scatter(const int* __restrict__ heads, const int* __restrict__ tails,
                          const int* __restrict__ etype, const int2* __restrict__ imat2) {
    for (int i = blockIdx.x * blockDim.x + threadIdx.x; i < NEDGE; i += gridDim.x * blockDim.x) {
        int h = heads[i];
        int p = g_off[h] + atomicAdd(&g_cur[h], 1);
        g_perm[p] = (tails[i] << 5) | etype[i];
        int2 rc = imat2[i];
        int r = SEG_U + rc.x;
        p = g_off[r] + atomicAdd(&g_cur[r], 1);
        g_perm[p] = rc.y;
        int c = SEG_I + rc.y;
        p = g_off[c] + atomicAdd(&g_cur[c], 1);
        g_perm[p] = rc.x;
    }
}

// entity aggregation: warp-per-entity, LOW-SMEM (s_rel only, 8KB -> full occupancy).
// Matvec reads transposed weights from global (L1-resident, coalesced per k).
__global__ void k_entity(const float* __restrict__ ext_ent, int hop,
                         const float* __restrict__ relw,
                         const float* __restrict__ b1, const float* __restrict__ b2,
                         float* __restrict__ out) {
    __shared__ float s_rel[NR * DM];
    int t = threadIdx.x;
    for (int i = t; i < NR * DM; i += blockDim.x) s_rel[i] = relw[i];
    __syncthreads();

    const float* entin = hop ? g_entB : ext_ent;
    float* entout      = hop ? g_entA : g_entB;
    const float* Wt1 = g_W1t[hop];
    const float* Wt2 = g_W2t[hop];

    int lane = t & 31;
    int e = blockIdx.x * (blockDim.x >> 5) + (t >> 5);
    if (e >= NE) return;
    int p0 = g_off[e], p1 = g_off[e + 1];
    bool eItem = e < NI;

    float a10 = 0, a11 = 0, a20 = 0, a21 = 0, ar0 = 0, ar1 = 0;
    int nc = 0;
    for (int p = p0; p < p1; p++) {
        int packed = g_perm[p];
        int tl = packed >> 5, ty = packed & 31;
        float r0 = s_rel[ty * 64 + lane], r1 = s_rel[ty * 64 + 32 + lane];
        float t0 = entin[tl * 64 + lane], t1 = entin[tl * 64 + 32 + lane];
        bool cross = eItem != (tl < NI);
        if (cross) { a10 += t0 * r0; a11 += t1 * r1; nc++; }
        else       { a20 += t0 + r0; a21 += t1 + r1; }
        ar0 += r0; ar1 += r1;
    }
    int n = p1 - p0;

    if (eItem) {
        float dn = 1.f / fmaxf((float)n, 1.f);
        float e0 = entin[e * 64 + lane], e1 = entin[e * 64 + 32 + lane];
        g_relkg_h[e * 64 + lane]      = __float2half((ar0 * dn) * e0);
        g_relkg_h[e * 64 + 32 + lane] = __float2half((ar1 * dn) * e1);
        g_kg_h[e * 64 + lane]         = __float2half(e0);
        g_kg_h[e * 64 + 32 + lane]    = __float2half(e1);
    }

    float i1 = 1.f / fmaxf((float)nc, 1.f);
    float i2 = 1.f / fmaxf((float)(n - nc), 1.f);
    a10 *= i1; a11 *= i1; a20 *= i2; a21 *= i2;

    float o10 = __ldg(&b1[lane]), o11 = __ldg(&b1[lane + 32]);
    float o20 = __ldg(&b2[lane]), o21 = __ldg(&b2[lane + 32]);
    #pragma unroll
    for (int k = 0; k < 64; k++) {
        float a1 = __shfl_sync(0xffffffffu, (k < 32) ? a10 : a11, k & 31);
        float a2 = __shfl_sync(0xffffffffu, (k < 32) ? a20 : a21, k & 31);
        o10 += a1 * __ldg(&Wt1[k * 64 + lane]);
        o11 += a1 * __ldg(&Wt1[k * 64 + 32 + lane]);
        o20 += a2 * __ldg(&Wt2[k * 64 + lane]);
        o21 += a2 * __ldg(&Wt2[k * 64 + 32 + lane]);
    }
    float v0 = 0.5f * (lrelu(o10) + lrelu(o20));
    float v1 = 0.5f * (lrelu(o11) + lrelu(o21));
    float ss = warpsum(v0 * v0 + v1 * v1);
    float inv = 1.f / fmaxf(sqrtf(ss), 1e-12f);
    v0 *= inv; v1 *= inv;
    entout[e * 64 + lane] = v0;
    entout[e * 64 + 32 + lane] = v1;
    out[e * 64 + lane] += v0;
    out[e * 64 + 32 + lane] += v1;
}

// fused USER + ITEM kernel (R11/R12-proven).
__global__ void __launch_bounds__(256) k_useritem(
        const float* __restrict__ ext_user, const float* __restrict__ ext_ucf,
        int hop, float* __restrict__ out)
{
    __shared__ __align__(16) float sm[8 * 320];   // per warp: U64|UC64|W64|WC64|COL64

    int w = threadIdx.x >> 5, lane = threadIdx.x & 31;

    if (blockIdx.x >= USER_BLOCKS) {
        // ---------------- item path ----------------
        const float2* ucfin2 = (const float2*)(hop ? g_ucf0 : ext_ucf);
        float2* out2 = (float2*)out;
        int c = (blockIdx.x - USER_BLOCKS) * 8 + w;
        if (c >= NI) return;
        int p0 = g_off[SEG_I + c], p1 = g_off[SEG_I + c + 1];
        float2 acc = make_float2(0.f, 0.f);
        for (int p = p0; p < p1; p++) {
            int row = g_perm[p];
            float2 v = ucfin2[row * 32 + lane];
            acc.x += v.x; acc.y += v.y;
        }
        float dn = 1.f / fmaxf((float)(p1 - p0), 1.f);
        acc.x *= dn; acc.y *= dn;
        float ss = warpsum(acc.x * acc.x + acc.y * acc.y);
        float inv = 1.f / fmaxf(sqrtf(ss), 1e-12f);
        acc.x *= inv; acc.y *= inv;
        ((__half2*)g_icf_h[(hop + 1) & 1])[c * 32 + lane] = __floats2half2_rn(acc.x, acc.y);
        int ob = (NE + 2 * NU) * 32 + c * 32 + lane;
        float2 o = out2[ob];
        o.x += acc.x; o.y += acc.y;
        out2[ob] = o;
        return;
    }

    // ---------------- user path ----------------
    const __half* icf_tab = g_icf_h[hop & 1];
    const uint4* rkh4    = (const uint4*)g_relkg_h;
    const uint4* icfh4   = (const uint4*)icf_tab;
    const __half2* rkh2  = (const __half2*)g_relkg_h;
    const __half2* kgh2  = (const __half2*)g_kg_h;
    const __half2* icfh2 = (const __half2*)icf_tab;
    const float* usrc    = hop ? g_u    : ext_user;
    const float* ucfsrc  = hop ? g_ucf0 : ext_ucf;
    float2* udst2   = (float2*)g_u;
    float2* ucfdst2 = (float2*)(hop ? g_ucf1 : g_ucf0);
    float2* out2    = (float2*)out;

    int u = blockIdx.x * 8 + w;
    if (u >= NU) return;

    float* sU  = sm + w * 320;
    float* sUC = sU + 64;
    float* sW  = sU + 128;
    float* sWC = sU + 192;
    int*   sCol = (int*)(sU + 256);

    int p0 = g_off[SEG_U + u];
    int n  = g_off[SEG_U + u + 1] - p0;
    if (n == 0) {
        float2 z = make_float2(0.f, 0.f);
        udst2[u * 32 + lane] = z;
        ucfdst2[u * 32 + lane] = z;
        return;
    }
    int pb = p0 - NEDGE;
    int nin = n < 64 ? n : 64;

    sU[lane]       = usrc[u * 64 + lane];
    sU[32 + lane]  = usrc[u * 64 + 32 + lane];
    sUC[lane]      = ucfsrc[u * 64 + lane];
    sUC[32 + lane] = ucfsrc[u * 64 + 32 + lane];
    if (lane < nin)      sCol[lane]      = g_perm[p0 + lane];
    if (lane + 32 < nin) sCol[lane + 32] = g_perm[p0 + lane + 32];
    __syncwarp();

    float2 ud, cd;
    int li = lane & 7, g = lane >> 3;

    for (int it = 0; it < 3; it++) {
        // ---- pass 1: dots, 4 pairs per warp (8 lanes each), half rows ----
        for (int jb = 0; jb < nin; jb += 4) {
            int j = jb + g;
            bool act = j < nin;
            int col = act ? sCol[j] : 0;
            uint4 ra = rkh4[col * 8 + li];
            uint4 ba = icfh4[col * 8 + li];
            float2 r0 = __half22float2(*(const __half2*)&ra.x);
            float2 r1 = __half22float2(*(const __half2*)&ra.y);
            float2 r2 = __half22float2(*(const __half2*)&ra.z);
            float2 r3 = __half22float2(*(const __half2*)&ra.w);
            float2 b0 = __half22float2(*(const __half2*)&ba.x);
            float2 b1 = __half22float2(*(const __half2*)&ba.y);
            float2 b2 = __half22float2(*(const __half2*)&ba.z);
            float2 b3 = __half22float2(*(const __half2*)&ba.w);
            float4 u0 = *(const float4*)(sU + 8 * li);
            float4 u1 = *(const float4*)(sU + 8 * li + 4);
            float4 c0 = *(const float4*)(sUC + 8 * li);
            float4 c1 = *(const float4*)(sUC + 8 * li + 4);
            float s  = r0.x*u0.x + r0.y*u0.y + r1.x*u0.z + r1.y*u0.w
                     + r2.x*u1.x + r2.y*u1.y + r3.x*u1.z + r3.y*u1.w;
            float sc = b0.x*c0.x + b0.y*c0.y + b1.x*c0.z + b1.y*c0.w
                     + b2.x*c1.x + b2.y*c1.y + b3.x*c1.z + b3.y*c1.w;
            s  += __shfl_xor_sync(0xffffffffu, s, 1);
            sc += __shfl_xor_sync(0xffffffffu, sc, 1);
            s  += __shfl_xor_sync(0xffffffffu, s, 2);
            sc += __shfl_xor_sync(0xffffffffu, sc, 2);
            s  += __shfl_xor_sync(0xffffffffu, s, 4);
            sc += __shfl_xor_sync(0xffffffffu, sc, 4);
            if (li == 0 && act) { sW[j] = s; sWC[j] = sc; }
        }
        for (int j = 64; j < n; j++) {   // fallback (not taken for this data)
            int col = g_perm[p0 + j];
            float2 rk = __half22float2(rkh2[col * 32 + lane]);
            float2 iv = __half22float2(icfh2[col * 32 + lane]);
            float s  = warpsum(rk.x * sU[2 * lane] + rk.y * sU[2 * lane + 1]);
            float sc = warpsum(iv.x * sUC[2 * lane] + iv.y * sUC[2 * lane + 1]);
            if (lane == 0) { g_p[pb + j] = s; g_pcf[pb + j] = sc; }
        }
        __syncwarp();
        // ---- pass 2: weights = exp(sigmoid(dot)) (max-free, exact) ----
        float se = 0.f, sec = 0.f;
        if (lane < nin) {
            float e  = __expf(sigmoidf(sW[lane]));
            float ec = __expf(sigmoidf(sWC[lane]));
            sW[lane] = e; sWC[lane] = ec; se += e; sec += ec;
        }
        if (lane + 32 < nin) {
            float e  = __expf(sigmoidf(sW[lane + 32]));
            float ec = __expf(sigmoidf(sWC[lane + 32]));
            sW[lane + 32] = e; sWC[lane + 32] = ec; se += e; sec += ec;
        }
        for (int j = 64 + lane; j < n; j += 32) {
            float e  = __expf(sigmoidf(g_p[pb + j]));
            float ec = __expf(sigmoidf(g_pcf[pb + j]));
            g_p[pb + j] = e; g_pcf[pb + j] = ec;
            se += e; sec += ec;
        }
        se = warpsum(se); sec = warpsum(sec);
        float inv = 1.f / se, invc = 1.f / sec;
        __syncwarp();
        // ---- pass 3: weighted accumulation (half rows) ----
        float2 A = make_float2(0.f, 0.f), B = make_float2(0.f, 0.f);
        for (int j = 0; j < nin; j++) {
            int col = sCol[j];
            float wp = sW[j] * inv, wc = sWC[j] * invc;
            float2 gv = __half22float2(kgh2[col * 32 + lane]);
            float2 iv = __half22float2(icfh2[col * 32 + lane]);
            A.x += wp * gv.x; A.y += wp * gv.y;
            B.x += wc * iv.x; B.y += wc * iv.y;
        }
        for (int j = 64; j < n; j++) {
            float wp = g_p[pb + j] * inv, wc = g_pcf[pb + j] * invc;
            int col = g_perm[p0 + j];
            float2 gv = __half22float2(kgh2[col * 32 + lane]);
            float2 iv = __half22float2(icfh2[col * 32 + lane]);
            A.x += wp * gv.x; A.y += wp * gv.y;
            B.x += wc * iv.x; B.y += wc * iv.y;
        }
        float ss = warpsum(A.x * A.x + A.y * A.y);
        float i1 = 1.f / fmaxf(sqrtf(ss), 1e-12f);
        ss = warpsum(B.x * B.x + B.y * B.y);
        float i2 = 1.f / fmaxf(sqrtf(ss), 1e-12f);
        ud.x = A.x * i1; ud.y = A.y * i1;
        cd.x = B.x * i2; cd.y = B.y * i2;
        if (it < 2) {
            __syncwarp();
            sU[2 * lane] = ud.x;  sU[2 * lane + 1] = ud.y;
            sUC[2 * lane] = cd.x; sUC[2 * lane + 1] = cd.y;
            __syncwarp();
        }
    }

    udst2[u * 32 + lane] = ud;
    ucfdst2[u * 32 + lane] = cd;
    int o1 = NE * 32 + u * 32 + lane;
    float2 o = out2[o1]; o.x += ud.x; o.y += ud.y; out2[o1] = o;
    int o2 = (NE + NU) * 32 + u * 32 + lane;
    o = out2[o2]; o.x += cd.x; o.y += cd.y; out2[o2] = o;
}

extern "C" void kernel_launch(void* const* d_in, const int* in_sizes, int n_in,
                              void* d_out, int out_size) {
    const float* user_emb = (const float*)d_in[0];
    const float* entity_emb = (const float*)d_in[1];
    const float* emb_cf = (const float*)d_in[2];
    const float* relw = (const float*)d_in[3];
    const float* W1 = (const float*)d_in[4];
    const float* B1 = (const float*)d_in[5];
    const float* W2 = (const float*)d_in[6];
    const float* B2 = (const float*)d_in[7];
    const int* eidx = (const int*)d_in[8];
    const int* etype = (const int*)d_in[9];
    const int* imat = (const int*)d_in[10];
    float* out = (float*)d_out;

    const int* heads = eidx;
    const int* tails = eidx + NEDGE;
    const float* ucf_ext = emb_cf;
    const int2* imat2 = (const int2*)imat;

    k_init<<<2048, 256>>>(user_emb, entity_emb, emb_cf, W1, W2, out);
    k_count<<<3907, 256>>>(heads, imat2);
    k_scan1<<<SCAN_NBLK, SCAN_BLK>>>();
    k_scanB<<<SCAN_NBLK, SCAN_BLK>>>();
    k_scatter<<<3907, 256>>>(heads, tails, etype, imat2);

    for (int h = 0; h < 2; h++) {
        k_entity<<<NE / 8, 256>>>(entity_emb, h, relw,
                                  B1 + h * DM, B2 + h * DM, out);
        k_useritem<<<USER_BLOCKS + ITEM_BLOCKS, 256>>>(user_emb, ucf_ext, h, out);
    }
    (void)in_sizes; (void)n_in; (void)out_size;
}